// round 16
// baseline (speedup 1.0000x reference)
#include <cuda_runtime.h>
#include <cuda_fp16.h>
#include <cstdint>

// ============================================================================
// Problem dims (fixed by the dataset)
// ============================================================================
#define N_TOK   4096      // B*S = 2*2048
#define V_DIM   32000
#define K_DIM   1024
#define EPSF    1e-5f
#define K0_CONST 12.8992199f   // ln(4/eps) = ln(400000)

// GEMM tiling — fp16 x fp16 -> fp16 m16n8k16, warp tile 64x32, 3 CTAs/SM,
// issue-spread (R15 champion).  NEW: balanced persistent grid (456 = 3x152
// SMs); at kt==15 the issue-halves target the NEXT tile's k0 chunk, so the
// cp.async ring never drains and the 0.54-empty tail wave disappears.
#define BM      128
#define BN      128
#define BK      64                 // fp16 per K-chunk = 128 bytes/row
#define KITERS  (K_DIM / BK)       // 16
#define STAGES  2
#define THREADS 256

#define MTILES  (N_TOK / BM)                 // 32
#define NTILES  ((N_TOK / BM) * (V_DIM / BN))// 8000
#define GRID    456                          // 3 CTAs/SM x 152 SMs (GB300)

#define A_BYTES     (BM * BK * 2)            // 16384
#define B_BYTES     (BN * BK * 2)            // 16384
#define STAGE_BYTES (A_BYTES + B_BYTES)      // 32768
#define TABLE_BYTES ((BM + BN) * 2 * 4)      // 2048
#define SMEM_DYN    (128 + STAGES * STAGE_BYTES + TABLE_BYTES)   // ~67.7 KB

// prep: 8 rows per 256-thread block (one warp per row)
#define PREP_ROWS_TOT (N_TOK + V_DIM)        // 36096
#define PREP_GRID     (PREP_ROWS_TOT / 8)    // 4512

// ============================================================================
// Device-global scratch (allocation-free rule: __device__ arrays)
// ============================================================================
__device__ __align__(128) __half g_xb[(size_t)N_TOK * K_DIM];   //  8 MB
__device__ __align__(128) __half g_yb[(size_t)V_DIM * K_DIM];   // 64 MB
__device__ float g_xsq[N_TOK];
__device__ float g_Ax[N_TOK];     // (1 - xsq) * 1e5
__device__ float g_ysq[V_DIM];
__device__ float g_By[V_DIM];     // (1 - ysq)

// ============================================================================
// PTX helpers (base-target only: cp.async, ldmatrix, mma.sync)
// ============================================================================
__device__ __forceinline__ uint32_t smem_u32(const void* p) {
    uint32_t a;
    asm("{ .reg .u64 t; cvta.to.shared.u64 t, %1; cvt.u32.u64 %0, t; }"
        : "=r"(a) : "l"(p));
    return a;
}

#define CP_ASYNC16(saddr, gptr) \
    asm volatile("cp.async.cg.shared.global [%0], [%1], 16;" \
                 :: "r"(saddr), "l"(gptr) : "memory")
#define CP_COMMIT() asm volatile("cp.async.commit_group;" ::: "memory")
#define CP_WAIT0()  asm volatile("cp.async.wait_group 0;" ::: "memory")

#define LDSM4(r0, r1, r2, r3, addr) \
    asm volatile("ldmatrix.sync.aligned.m8n8.x4.shared.b16 {%0,%1,%2,%3}, [%4];" \
                 : "=r"(r0), "=r"(r1), "=r"(r2), "=r"(r3) : "r"(addr))

// f16 x f16 -> f16 accumulate: D fragment = 2 packed-half regs
#define MMA16816H(c, a, b0, b1) \
    asm volatile("mma.sync.aligned.m16n8k16.row.col.f16.f16.f16.f16 " \
                 "{%0,%1}, {%2,%3,%4,%5}, {%6,%7}, {%0,%1};" \
                 : "+r"((c)[0]), "+r"((c)[1]) \
                 : "r"((a)[0]), "r"((a)[1]), "r"((a)[2]), "r"((a)[3]), \
                   "r"(b0), "r"(b1))

// ============================================================================
// Fused prep kernel: one warp per row, 8 rows per block, both tensors.
// ============================================================================
__global__ void __launch_bounds__(256) prep_all(const float* __restrict__ hidden,
                                                const float* __restrict__ weight) {
    const int lane = threadIdx.x & 31;
    const int w    = threadIdx.x >> 5;
    const int row  = blockIdx.x * 8 + w;

    const bool isx = (row < N_TOK);
    const int  r   = isx ? row : row - N_TOK;
    const float4* src = reinterpret_cast<const float4*>(isx ? hidden : weight)
                        + (size_t)r * 256;

    float4 v[8];
    #pragma unroll
    for (int j = 0; j < 8; ++j) v[j] = src[j * 32 + lane];

    float ss = 0.f;
    #pragma unroll
    for (int j = 0; j < 8; ++j)
        ss += fmaf(v[j].x, v[j].x, fmaf(v[j].y, v[j].y,
              fmaf(v[j].z, v[j].z, v[j].w * v[j].w)));
    #pragma unroll
    for (int o = 16; o; o >>= 1) ss += __shfl_xor_sync(0xFFFFFFFFu, ss, o);

    const float norm  = sqrtf(ss);
    const float scale = fminf((1.0f - EPSF) / (norm + 1e-10f), 1.0f);
    const float sq    = scale * scale * ss;

    if (lane == 0) {
        if (isx) { g_xsq[r] = sq; g_Ax[r] = (1.0f - sq) * 1e5f; }
        else     { g_ysq[r] = sq; g_By[r] = (1.0f - sq); }
    }

    uint2* dst = reinterpret_cast<uint2*>(isx ? g_xb : g_yb) + (size_t)r * 256;
    #pragma unroll
    for (int j = 0; j < 8; ++j) {
        __half2 h0 = __float22half2_rn(make_float2(v[j].x * scale, v[j].y * scale));
        __half2 h1 = __float22half2_rn(make_float2(v[j].z * scale, v[j].w * scale));
        uint2 u;
        u.x = *reinterpret_cast<uint32_t*>(&h0);
        u.y = *reinterpret_cast<uint32_t*>(&h1);
        dst[j * 32 + lane] = u;
    }
}

// ============================================================================
// Hyperbolic epilogue transform (fast closed form; guarded exact path)
// ============================================================================
__device__ __forceinline__ float hyp(float g, float xs, float An,
                                     float ys, float By) {
    const float d2 = fmaf(-2.0f, g, xs + ys);
    const float ab = An * By;       // (1-xs)(1-ys)/eps
    if (d2 > 0.25f && ab < 0.01f) {
        // -acosh(1 + 2*sqrt(d2)/(denom+eps)) ~= ab - ln(4/eps) - 0.5*ln(d2)
        return fmaf(-0.5f, __logf(d2), ab - K0_CONST);
    }
    const float dist  = sqrtf(fmaxf(d2, 0.0f));
    const float denom = (An * EPSF) * By + EPSF;
    const float arg   = fmaxf(1.0f + 2.0f * dist / denom, 1.0f + EPSF);
    return -acoshf(arg);
}

// ============================================================================
// Persistent fused GEMM + epilogue.  grid 456, 256 threads, 3 CTAs/SM.
// Warp grid 2(M) x 4(N); warp tile 64x32; fp16 accum (32 regs).
// 2-stage cp.async double buffer; issue spread over kk=0/kk=1; at kt==15 the
// issue targets the next tile's k0 chunk (ring never drains).
// ============================================================================
// phase 0: A rows [0,64) + B rows [0,64); phase 1: the other halves.
__device__ __forceinline__ void issue_half(uint32_t tiles, int s, int kt,
                                           const char* gA, const char* gB,
                                           int tid, int phase) {
    const uint32_t aSt = tiles + (uint32_t)s * STAGE_BYTES;
    const uint32_t bSt = aSt + A_BYTES;
    const size_t kOff = (size_t)kt * (BK * 2);    // 128 bytes into the row
    #pragma unroll
    for (int t = 0; t < 2; ++t) {                 // A half: 64 rows x 8 chunks
        const int idx = (phase * 2 + t) * THREADS + tid;
        const int row = idx >> 3, ch = idx & 7;
        const char* gp = gA + (size_t)row * (K_DIM * 2) + kOff + (size_t)ch * 16;
        const uint32_t sa = aSt + (uint32_t)(row * 128 + ((ch ^ (row & 7)) * 16));
        CP_ASYNC16(sa, gp);
    }
    #pragma unroll
    for (int t = 0; t < 2; ++t) {                 // B half: 64 rows x 8 chunks
        const int idx = (phase * 2 + t) * THREADS + tid;
        const int row = idx >> 3, ch = idx & 7;
        const char* gp = gB + (size_t)row * (K_DIM * 2) + kOff + (size_t)ch * 16;
        const uint32_t sa = bSt + (uint32_t)(row * 128 + ((ch ^ (row & 7)) * 16));
        CP_ASYNC16(sa, gp);
    }
}

__global__ void __launch_bounds__(THREADS, 3) hyper_gemm(float* __restrict__ out) {
    extern __shared__ char smem[];
    const uint32_t sb    = smem_u32(smem);
    const uint32_t tiles = (sb + 127) & ~127u;
    char* smemc = smem + (tiles - sb);

    float* sXs  = reinterpret_cast<float*>(smemc + STAGES * STAGE_BYTES);
    float* sAn  = sXs + BM;
    float* sYsq = sAn + BM;
    float* sBy  = sYsq + BN;

    const int tid  = threadIdx.x;
    const int lane = tid & 31;
    const int wid  = tid >> 5;
    const int wm   = wid >> 2;          // 0..1  (M direction, 64 rows each)
    const int wn   = wid & 3;           // 0..3  (N direction, 32 cols each)

    // per-thread ldmatrix address components
    const int aRowB = wm * 64 + (lane & 15);                        // + i*16
    const int aChB  = lane >> 4;                                    // + 2*kk
    const int bRowB = wn * 32 + (lane & 7) + ((lane >> 4) << 3);    // + jp*16
    const int bChB  = (lane >> 3) & 1;                              // + 2*kk
    const int swz   = lane & 7;
    // epilogue coordinates
    const int rBase = wm * 64 + (lane >> 2);        // + i*16 (+8)
    const int cBase = wn * 32 + (lane & 3) * 2;     // + j*8

    int t = blockIdx.x;                  // current tile (m fastest, 32 m-tiles)
    int m0 = (t & (MTILES - 1)) * BM;
    int v0 = (t >> 5) * BN;
    const char* gA = reinterpret_cast<const char*>(g_xb) + (size_t)m0 * (K_DIM * 2);
    const char* gB = reinterpret_cast<const char*>(g_yb) + (size_t)v0 * (K_DIM * 2);

    // prologue: fill stage 0 of the first tile
    issue_half(tiles, 0, 0, gA, gB, tid, 0);
    issue_half(tiles, 0, 0, gA, gB, tid, 1);
    CP_COMMIT();

    while (true) {
        // epilogue tables for THIS tile (first tile: no prior readers;
        // later tiles: end-of-epilogue __syncthreads ordered the overwrite)
        if (tid < BM) { sXs[tid] = g_xsq[m0 + tid]; sAn[tid] = g_Ax[m0 + tid]; }
        else { const int c = tid - BM; sYsq[c] = g_ysq[v0 + c]; sBy[c] = g_By[v0 + c]; }

        uint32_t acc[4][4][2] = {};      // packed-half accumulators (32 regs)

        #pragma unroll 1
        for (int kt = 0; kt < KITERS; ++kt) {
            CP_WAIT0();              // stage kt's group fully landed
            __syncthreads();         // readers of stage s^1 done; tables live

            const int s = kt & 1;
            const uint32_t aSt = tiles + (uint32_t)s * STAGE_BYTES;
            const uint32_t bSt = aSt + A_BYTES;

            // next chunk to issue: (tile, kt+1), or (tile+GRID, 0) at kt==15
            const char *giA = gA, *giB = gB;
            int kIss = kt + 1;
            bool more = true;
            if (kt == KITERS - 1) {
                const int tn = t + GRID;
                more = (tn < NTILES);
                if (more) {
                    giA = reinterpret_cast<const char*>(g_xb)
                          + (size_t)((tn & (MTILES - 1)) * BM) * (K_DIM * 2);
                    giB = reinterpret_cast<const char*>(g_yb)
                          + (size_t)((tn >> 5) * BN) * (K_DIM * 2);
                }
                kIss = 0;
            }

            #pragma unroll
            for (int kk = 0; kk < 4; ++kk) {     // 4 x k16 per 64-elt chunk
                if (kk < 2 && more)
                    issue_half(tiles, s ^ 1, kIss, giA, giB, tid, kk);

                uint32_t af[4][4];
                #pragma unroll
                for (int i = 0; i < 4; ++i) {
                    const uint32_t addr = aSt
                        + (uint32_t)((aRowB + i * 16) * 128)
                        + (uint32_t)((((kk * 2 + aChB) ^ swz) * 16));
                    LDSM4(af[i][0], af[i][1], af[i][2], af[i][3], addr);
                }
                uint32_t bf[2][4];
                #pragma unroll
                for (int jp = 0; jp < 2; ++jp) {
                    const uint32_t addr = bSt
                        + (uint32_t)((bRowB + jp * 16) * 128)
                        + (uint32_t)((((kk * 2 + bChB) ^ swz) * 16));
                    LDSM4(bf[jp][0], bf[jp][1], bf[jp][2], bf[jp][3], addr);
                }
                #pragma unroll
                for (int i = 0; i < 4; ++i)
                    #pragma unroll
                    for (int j = 0; j < 4; ++j)
                        MMA16816H(acc[i][j], af[i],
                                  bf[j >> 1][(j & 1) * 2],
                                  bf[j >> 1][(j & 1) * 2 + 1]);
            }
            CP_COMMIT();             // one group per kt
        }

        // ---------------- epilogue: transform + store ----------------
        #pragma unroll
        for (int i = 0; i < 4; ++i) {
            const int ra = rBase + i * 16;
            const int rb = ra + 8;
            const float xsa = sXs[ra], Ana = sAn[ra];
            const float xsb = sXs[rb], Anb = sAn[rb];
            float* outA = out + (size_t)(m0 + ra) * V_DIM + v0;
            float* outB = out + (size_t)(m0 + rb) * V_DIM + v0;
            #pragma unroll
            for (int j = 0; j < 4; ++j) {
                const int lc = cBase + j * 8;
                const float ys0 = sYsq[lc],     By0 = sBy[lc];
                const float ys1 = sYsq[lc + 1], By1 = sBy[lc + 1];
                const float2 ga = __half22float2(
                    *reinterpret_cast<const __half2*>(&acc[i][j][0]));
                const float2 gb = __half22float2(
                    *reinterpret_cast<const __half2*>(&acc[i][j][1]));
                float2 pa, pb;
                pa.x = hyp(ga.x, xsa, Ana, ys0, By0);
                pa.y = hyp(ga.y, xsa, Ana, ys1, By1);
                pb.x = hyp(gb.x, xsb, Anb, ys0, By0);
                pb.y = hyp(gb.y, xsb, Anb, ys1, By1);
                *reinterpret_cast<float2*>(outA + lc) = pa;
                *reinterpret_cast<float2*>(outB + lc) = pb;
            }
        }

        t += GRID;
        if (t >= NTILES) break;
        m0 = (t & (MTILES - 1)) * BM;
        v0 = (t >> 5) * BN;
        gA = reinterpret_cast<const char*>(g_xb) + (size_t)m0 * (K_DIM * 2);
        gB = reinterpret_cast<const char*>(g_yb) + (size_t)v0 * (K_DIM * 2);
        __syncthreads();   // epilogue table reads done before next overwrite
    }
}

// ============================================================================
// Launch
// ============================================================================
extern "C" void kernel_launch(void* const* d_in, const int* in_sizes, int n_in,
                              void* d_out, int out_size) {
    const float* hidden = (const float*)d_in[0];
    const float* weight = (const float*)d_in[1];
    float* out = (float*)d_out;

    prep_all<<<PREP_GRID, 256>>>(hidden, weight);

    cudaFuncSetAttribute(hyper_gemm,
                         cudaFuncAttributeMaxDynamicSharedMemorySize, SMEM_DYN);
    hyper_gemm<<<GRID, THREADS, SMEM_DYN>>>(out);
}

// round 17
// speedup vs baseline: 1.1592x; 1.1592x over previous
#include <cuda_runtime.h>
#include <cuda_fp16.h>
#include <cstdint>

// ============================================================================
// Problem dims (fixed by the dataset)
// ============================================================================
#define N_TOK   4096      // B*S = 2*2048
#define V_DIM   32000
#define K_DIM   1024
#define EPSF    1e-5f
#define K0_CONST 12.8992199f   // ln(4/eps) = ln(400000)

// GEMM tiling — fp16 x fp16 -> fp16 m16n8k16, warp tile 64x32, 3 CTAs/SM
// (R15 champion structure; persistence re-confirmed as a regression twice).
// NEW: issue halves spread at kk=0 and kk=2 (uniform LSU pressure) and kt
// loop unrolled x2 (compile-time stage index).
#define BM      128
#define BN      128
#define BK      64                 // fp16 per K-chunk = 128 bytes/row
#define KITERS  (K_DIM / BK)       // 16
#define STAGES  2
#define THREADS 256

#define A_BYTES     (BM * BK * 2)            // 16384
#define B_BYTES     (BN * BK * 2)            // 16384
#define STAGE_BYTES (A_BYTES + B_BYTES)      // 32768
#define TABLE_BYTES ((BM + BN) * 2 * 4)      // 2048
#define SMEM_DYN    (128 + STAGES * STAGE_BYTES + TABLE_BYTES)   // ~67.7 KB

// prep: 8 rows per 256-thread block (one warp per row)
#define PREP_ROWS_TOT (N_TOK + V_DIM)        // 36096
#define PREP_GRID     (PREP_ROWS_TOT / 8)    // 4512

// ============================================================================
// Device-global scratch (allocation-free rule: __device__ arrays)
// ============================================================================
__device__ __align__(128) __half g_xb[(size_t)N_TOK * K_DIM];   //  8 MB
__device__ __align__(128) __half g_yb[(size_t)V_DIM * K_DIM];   // 64 MB
__device__ float g_xsq[N_TOK];
__device__ float g_Ax[N_TOK];     // (1 - xsq) * 1e5
__device__ float g_ysq[V_DIM];
__device__ float g_By[V_DIM];     // (1 - ysq)

// ============================================================================
// PTX helpers (base-target only: cp.async, ldmatrix, mma.sync)
// ============================================================================
__device__ __forceinline__ uint32_t smem_u32(const void* p) {
    uint32_t a;
    asm("{ .reg .u64 t; cvta.to.shared.u64 t, %1; cvt.u32.u64 %0, t; }"
        : "=r"(a) : "l"(p));
    return a;
}

#define CP_ASYNC16(saddr, gptr) \
    asm volatile("cp.async.cg.shared.global [%0], [%1], 16;" \
                 :: "r"(saddr), "l"(gptr) : "memory")
#define CP_COMMIT() asm volatile("cp.async.commit_group;" ::: "memory")
#define CP_WAIT0()  asm volatile("cp.async.wait_group 0;" ::: "memory")

#define LDSM4(r0, r1, r2, r3, addr) \
    asm volatile("ldmatrix.sync.aligned.m8n8.x4.shared.b16 {%0,%1,%2,%3}, [%4];" \
                 : "=r"(r0), "=r"(r1), "=r"(r2), "=r"(r3) : "r"(addr))

// f16 x f16 -> f16 accumulate: D fragment = 2 packed-half regs
#define MMA16816H(c, a, b0, b1) \
    asm volatile("mma.sync.aligned.m16n8k16.row.col.f16.f16.f16.f16 " \
                 "{%0,%1}, {%2,%3,%4,%5}, {%6,%7}, {%0,%1};" \
                 : "+r"((c)[0]), "+r"((c)[1]) \
                 : "r"((a)[0]), "r"((a)[1]), "r"((a)[2]), "r"((a)[3]), \
                   "r"(b0), "r"(b1))

// ============================================================================
// Fused prep kernel: one warp per row, 8 rows per block, both tensors.
// ============================================================================
__global__ void __launch_bounds__(256) prep_all(const float* __restrict__ hidden,
                                                const float* __restrict__ weight) {
    const int lane = threadIdx.x & 31;
    const int w    = threadIdx.x >> 5;
    const int row  = blockIdx.x * 8 + w;

    const bool isx = (row < N_TOK);
    const int  r   = isx ? row : row - N_TOK;
    const float4* src = reinterpret_cast<const float4*>(isx ? hidden : weight)
                        + (size_t)r * 256;

    float4 v[8];
    #pragma unroll
    for (int j = 0; j < 8; ++j) v[j] = src[j * 32 + lane];

    float ss = 0.f;
    #pragma unroll
    for (int j = 0; j < 8; ++j)
        ss += fmaf(v[j].x, v[j].x, fmaf(v[j].y, v[j].y,
              fmaf(v[j].z, v[j].z, v[j].w * v[j].w)));
    #pragma unroll
    for (int o = 16; o; o >>= 1) ss += __shfl_xor_sync(0xFFFFFFFFu, ss, o);

    const float norm  = sqrtf(ss);
    const float scale = fminf((1.0f - EPSF) / (norm + 1e-10f), 1.0f);
    const float sq    = scale * scale * ss;

    if (lane == 0) {
        if (isx) { g_xsq[r] = sq; g_Ax[r] = (1.0f - sq) * 1e5f; }
        else     { g_ysq[r] = sq; g_By[r] = (1.0f - sq); }
    }

    uint2* dst = reinterpret_cast<uint2*>(isx ? g_xb : g_yb) + (size_t)r * 256;
    #pragma unroll
    for (int j = 0; j < 8; ++j) {
        __half2 h0 = __float22half2_rn(make_float2(v[j].x * scale, v[j].y * scale));
        __half2 h1 = __float22half2_rn(make_float2(v[j].z * scale, v[j].w * scale));
        uint2 u;
        u.x = *reinterpret_cast<uint32_t*>(&h0);
        u.y = *reinterpret_cast<uint32_t*>(&h1);
        dst[j * 32 + lane] = u;
    }
}

// ============================================================================
// Hyperbolic epilogue transform (fast closed form; guarded exact path)
// ============================================================================
__device__ __forceinline__ float hyp(float g, float xs, float An,
                                     float ys, float By) {
    const float d2 = fmaf(-2.0f, g, xs + ys);
    const float ab = An * By;       // (1-xs)(1-ys)/eps
    if (d2 > 0.25f && ab < 0.01f) {
        // -acosh(1 + 2*sqrt(d2)/(denom+eps)) ~= ab - ln(4/eps) - 0.5*ln(d2)
        return fmaf(-0.5f, __logf(d2), ab - K0_CONST);
    }
    const float dist  = sqrtf(fmaxf(d2, 0.0f));
    const float denom = (An * EPSF) * By + EPSF;
    const float arg   = fmaxf(1.0f + 2.0f * dist / denom, 1.0f + EPSF);
    return -acoshf(arg);
}

// ============================================================================
// Fused GEMM + epilogue.  grid (32, 250), 256 threads, 3 CTAs/SM.
// Warp grid 2(M) x 4(N); warp tile 64x32; fp16 accum (32 regs).
// 2-stage cp.async double buffer; issue halves at kk=0 and kk=2.
// ============================================================================
// phase 0: A rows [0,64) + B rows [0,64); phase 1: the other halves.
__device__ __forceinline__ void issue_half(uint32_t tiles, int s, int kt,
                                           const char* gA, const char* gB,
                                           int tid, int phase) {
    const uint32_t aSt = tiles + (uint32_t)s * STAGE_BYTES;
    const uint32_t bSt = aSt + A_BYTES;
    const size_t kOff = (size_t)kt * (BK * 2);    // 128 bytes into the row
    #pragma unroll
    for (int t = 0; t < 2; ++t) {                 // A half: 64 rows x 8 chunks
        const int idx = (phase * 2 + t) * THREADS + tid;
        const int row = idx >> 3, ch = idx & 7;
        const char* gp = gA + (size_t)row * (K_DIM * 2) + kOff + (size_t)ch * 16;
        const uint32_t sa = aSt + (uint32_t)(row * 128 + ((ch ^ (row & 7)) * 16));
        CP_ASYNC16(sa, gp);
    }
    #pragma unroll
    for (int t = 0; t < 2; ++t) {                 // B half: 64 rows x 8 chunks
        const int idx = (phase * 2 + t) * THREADS + tid;
        const int row = idx >> 3, ch = idx & 7;
        const char* gp = gB + (size_t)row * (K_DIM * 2) + kOff + (size_t)ch * 16;
        const uint32_t sa = bSt + (uint32_t)(row * 128 + ((ch ^ (row & 7)) * 16));
        CP_ASYNC16(sa, gp);
    }
}

__global__ void __launch_bounds__(THREADS, 3) hyper_gemm(float* __restrict__ out) {
    extern __shared__ char smem[];
    const uint32_t sb    = smem_u32(smem);
    const uint32_t tiles = (sb + 127) & ~127u;
    char* smemc = smem + (tiles - sb);

    float* sXs  = reinterpret_cast<float*>(smemc + STAGES * STAGE_BYTES);
    float* sAn  = sXs + BM;
    float* sYsq = sAn + BM;
    float* sBy  = sYsq + BN;

    const int tid  = threadIdx.x;
    const int lane = tid & 31;
    const int wid  = tid >> 5;
    const int wm   = wid >> 2;          // 0..1  (M direction, 64 rows each)
    const int wn   = wid & 3;           // 0..3  (N direction, 32 cols each)
    const int m0   = blockIdx.x * BM;
    const int v0   = blockIdx.y * BN;

    // epilogue tables
    if (tid < BM) { sXs[tid] = g_xsq[m0 + tid]; sAn[tid] = g_Ax[m0 + tid]; }
    else { const int c = tid - BM; sYsq[c] = g_ysq[v0 + c]; sBy[c] = g_By[v0 + c]; }

    const char* gA = reinterpret_cast<const char*>(g_xb) + (size_t)m0 * (K_DIM * 2);
    const char* gB = reinterpret_cast<const char*>(g_yb) + (size_t)v0 * (K_DIM * 2);

    // prologue: fill stage 0
    issue_half(tiles, 0, 0, gA, gB, tid, 0);
    issue_half(tiles, 0, 0, gA, gB, tid, 1);
    CP_COMMIT();

    uint32_t acc[4][4][2] = {};         // packed-half accumulators (32 regs)

    // per-thread ldmatrix address components
    const int aRowB = wm * 64 + (lane & 15);                        // + i*16
    const int aChB  = lane >> 4;                                    // + 2*kk
    const int bRowB = wn * 32 + (lane & 7) + ((lane >> 4) << 3);    // + jp*16
    const int bChB  = (lane >> 3) & 1;                              // + 2*kk
    const int swz   = lane & 7;

    #pragma unroll 2
    for (int kt = 0; kt < KITERS; ++kt) {
        CP_WAIT0();              // stage kt's group fully landed
        __syncthreads();         // all warps done reading previous stage

        const int s = kt & 1;    // compile-time under unroll-2
        const uint32_t aSt = tiles + (uint32_t)s * STAGE_BYTES;
        const uint32_t bSt = aSt + A_BYTES;
        const bool more = (kt + 1 < KITERS);

        #pragma unroll
        for (int kk = 0; kk < 4; ++kk) {         // 4 x k16 per 64-elt chunk
            // spread next-stage issues at kk=0 and kk=2 (uniform LSU load;
            // last issue still ~2 kk-groups ahead of its wait)
            if ((kk == 0 || kk == 2) && more)
                issue_half(tiles, s ^ 1, kt + 1, gA, gB, tid, kk >> 1);

            uint32_t af[4][4];
            #pragma unroll
            for (int i = 0; i < 4; ++i) {
                const uint32_t addr = aSt
                    + (uint32_t)((aRowB + i * 16) * 128)
                    + (uint32_t)((((kk * 2 + aChB) ^ swz) * 16));
                LDSM4(af[i][0], af[i][1], af[i][2], af[i][3], addr);
            }
            uint32_t bf[2][4];
            #pragma unroll
            for (int jp = 0; jp < 2; ++jp) {
                const uint32_t addr = bSt
                    + (uint32_t)((bRowB + jp * 16) * 128)
                    + (uint32_t)((((kk * 2 + bChB) ^ swz) * 16));
                LDSM4(bf[jp][0], bf[jp][1], bf[jp][2], bf[jp][3], addr);
            }
            #pragma unroll
            for (int i = 0; i < 4; ++i)
                #pragma unroll
                for (int j = 0; j < 4; ++j)
                    MMA16816H(acc[i][j], af[i],
                              bf[j >> 1][(j & 1) * 2],
                              bf[j >> 1][(j & 1) * 2 + 1]);
        }
        CP_COMMIT();             // one group per kt (may be empty on last)
    }

    // ---------------- epilogue: transform + store ----------------
    // f16 D fragment: reg0 = halves (row r, cols 2c,2c+1); reg1 = row r+8.
    const int rBase = wm * 64 + (lane >> 2);        // + i*16 (+8)
    const int cBase = wn * 32 + (lane & 3) * 2;     // + j*8

    #pragma unroll
    for (int i = 0; i < 4; ++i) {
        const int ra = rBase + i * 16;
        const int rb = ra + 8;
        const float xsa = sXs[ra], Ana = sAn[ra];
        const float xsb = sXs[rb], Anb = sAn[rb];
        float* outA = out + (size_t)(m0 + ra) * V_DIM + v0;
        float* outB = out + (size_t)(m0 + rb) * V_DIM + v0;
        #pragma unroll
        for (int j = 0; j < 4; ++j) {
            const int lc = cBase + j * 8;
            const float ys0 = sYsq[lc],     By0 = sBy[lc];
            const float ys1 = sYsq[lc + 1], By1 = sBy[lc + 1];
            const float2 ga = __half22float2(
                *reinterpret_cast<const __half2*>(&acc[i][j][0]));
            const float2 gb = __half22float2(
                *reinterpret_cast<const __half2*>(&acc[i][j][1]));
            float2 pa, pb;
            pa.x = hyp(ga.x, xsa, Ana, ys0, By0);
            pa.y = hyp(ga.y, xsa, Ana, ys1, By1);
            pb.x = hyp(gb.x, xsb, Anb, ys0, By0);
            pb.y = hyp(gb.y, xsb, Anb, ys1, By1);
            *reinterpret_cast<float2*>(outA + lc) = pa;
            *reinterpret_cast<float2*>(outB + lc) = pb;
        }
    }
}

// ============================================================================
// Launch
// ============================================================================
extern "C" void kernel_launch(void* const* d_in, const int* in_sizes, int n_in,
                              void* d_out, int out_size) {
    const float* hidden = (const float*)d_in[0];
    const float* weight = (const float*)d_in[1];
    float* out = (float*)d_out;

    prep_all<<<PREP_GRID, 256>>>(hidden, weight);

    cudaFuncSetAttribute(hyper_gemm,
                         cudaFuncAttributeMaxDynamicSharedMemorySize, SMEM_DYN);
    dim3 grid(N_TOK / BM, V_DIM / BN);   // (32, 250); m-fastest: A L2-resident
    hyper_gemm<<<grid, THREADS, SMEM_DYN>>>(out);
}